// round 9
// baseline (speedup 1.0000x reference)
#include <cuda_runtime.h>
#include <cstdint>

// Problem constants
#define B_   8
#define F_   32      // input channels
#define NN   256     // nodes
#define MM   64
#define CO   64      // output channels
#define CC   224     // concat channels = 7*32
#define XP   33      // padded pitch (floats) for transposed X tiles

typedef unsigned long long u64;

// ---- packed f32x2 helpers (FFMA2 path: ptxas never emits this from C++) ----
__device__ __forceinline__ u64 pack2(float lo, float hi) {
    u64 r; asm("mov.b64 %0, {%1, %2};" : "=l"(r) : "f"(lo), "f"(hi)); return r;
}
__device__ __forceinline__ float2 unpk2(u64 v) {
    float2 f; asm("mov.b64 {%0, %1}, %2;" : "=f"(f.x), "=f"(f.y) : "l"(v)); return f;
}
__device__ __forceinline__ u64 ffma2(u64 a, u64 b, u64 c) {
    u64 d; asm("fma.rn.f32x2 %0, %1, %2, %3;" : "=l"(d) : "l"(a), "l"(b), "l"(c)); return d;
}

// ---- cp.async ----
__device__ __forceinline__ void cp_async16(void* smem_dst, const void* gmem_src) {
    uint32_t s = (uint32_t)__cvta_generic_to_shared(smem_dst);
    asm volatile("cp.async.cg.shared.global [%0], [%1], 16;\n" :: "r"(s), "l"(gmem_src));
}
__device__ __forceinline__ void cp_commit() { asm volatile("cp.async.commit_group;\n"); }
template <int N>
__device__ __forceinline__ void cp_wait() { asm volatile("cp.async.wait_group %0;\n" :: "n"(N)); }

__device__ __forceinline__ void issue_panel_copy(float* dst, const float* src, int t) {
    const float4* s4 = (const float4*)src;
    float4* d4 = (float4*)dst;
#pragma unroll
    for (int i = 0; i < 4; ++i)           // 2048 float4 / 512 threads
        cp_async16(&d4[t + 512 * i], &s4[t + 512 * i]);
    cp_commit();
}

// X1[f][v] = sum_n X[f][n] * A[n][v].
// X tiles live TRANSPOSED in smem: XT[v or n][f], pitch XP=33 (conflict-free).
// Thread map: lane l -> rows {f0, f0+16}, cols [vb, vb+8). A reads are
// (half-)warp broadcasts; X reads are conflict-free LDS.32.
__device__ __forceinline__ void nconv_step(
    const float* __restrict__ Ag,    // global A[b][m]: [256][256]
    const float* Xsrc, float* Xdst,  // smem XT tiles [256][XP] (may alias)
    float* As0, float* As1,
    int t, int f0, int vb)
{
    u64 acc[2][4];
#pragma unroll
    for (int r = 0; r < 2; ++r)
#pragma unroll
        for (int p = 0; p < 4; ++p) acc[r][p] = 0ull;   // bits 0 == (0.f,0.f)

    float* bufs[2] = { As0, As1 };
    issue_panel_copy(As0, Ag, t);

#pragma unroll 1
    for (int kp = 0; kp < 8; ++kp) {
        if (kp < 7) {
            issue_panel_copy(bufs[(kp + 1) & 1], Ag + (kp + 1) * 8192, t);
            cp_wait<1>();
        } else {
            cp_wait<0>();
        }
        __syncthreads();

        const float* As = bufs[kp & 1];
        const float* Xk = Xsrc + (kp * 32) * XP + f0;
#pragma unroll 8
        for (int k = 0; k < 32; ++k) {
            const ulonglong2* ap = (const ulonglong2*)(As + k * NN + vb);
            ulonglong2 a01 = ap[0];      // cols vb..vb+3 (2 packed pairs)
            ulonglong2 a23 = ap[1];      // cols vb+4..vb+7
            float x0 = Xk[k * XP];
            float x1 = Xk[k * XP + 16];
            u64 x0p = pack2(x0, x0);
            u64 x1p = pack2(x1, x1);
            acc[0][0] = ffma2(x0p, a01.x, acc[0][0]);
            acc[0][1] = ffma2(x0p, a01.y, acc[0][1]);
            acc[0][2] = ffma2(x0p, a23.x, acc[0][2]);
            acc[0][3] = ffma2(x0p, a23.y, acc[0][3]);
            acc[1][0] = ffma2(x1p, a01.x, acc[1][0]);
            acc[1][1] = ffma2(x1p, a01.y, acc[1][1]);
            acc[1][2] = ffma2(x1p, a23.x, acc[1][2]);
            acc[1][3] = ffma2(x1p, a23.y, acc[1][3]);
        }
        __syncthreads();   // panel consumed (buffer reused at kp+2)
    }

    // All reads of Xsrc finished at the barrier above -> in-place safe.
#pragma unroll
    for (int p = 0; p < 4; ++p) {
        float2 v0 = unpk2(acc[0][p]);
        float2 v1 = unpk2(acc[1][p]);
        Xdst[(vb + 2 * p    ) * XP + f0]      = v0.x;
        Xdst[(vb + 2 * p + 1) * XP + f0]      = v0.y;
        Xdst[(vb + 2 * p    ) * XP + f0 + 16] = v1.x;
        Xdst[(vb + 2 * p + 1) * XP + f0 + 16] = v1.y;
    }
    __syncthreads();       // Xdst visible
}

// Y[o][v] += sum_c W[o][cb+c] * h[c][v], h[c][v] = Bs[v*XP + c] (transposed tile).
// Thread map: lane -> 8 o (4 packed pairs, vector-loaded from WT), 4 v (broadcast h).
__device__ __forceinline__ void mix_step(
    const float* Bs,                 // smem XT tile [256][XP]
    const float* WT,                 // smem W^T [224][64]
    int cb,
    u64 (&yacc)[4][4],
    int mvb, int ob)
{
#pragma unroll 4
    for (int c = 0; c < 32; ++c) {
        const ulonglong2* wp = (const ulonglong2*)(WT + (cb + c) * 64 + ob);
        ulonglong2 w01 = wp[0];      // o..o+3
        ulonglong2 w23 = wp[1];      // o+4..o+7
#pragma unroll
        for (int jj = 0; jj < 4; ++jj) {
            float h = Bs[(mvb + jj) * XP + c];
            u64 hp = pack2(h, h);
            yacc[jj][0] = ffma2(hp, w01.x, yacc[jj][0]);
            yacc[jj][1] = ffma2(hp, w01.y, yacc[jj][1]);
            yacc[jj][2] = ffma2(hp, w23.x, yacc[jj][2]);
            yacc[jj][3] = ffma2(hp, w23.y, yacc[jj][3]);
        }
    }
}

__global__ __launch_bounds__(512, 1)
void gcn_fused_kernel(
    const float* __restrict__ x,      // [8][32][256][64]
    const float* __restrict__ base0,  // [8][64][256][256]
    const float* __restrict__ base1,
    const float* __restrict__ base2,
    const float* __restrict__ W,      // [64][224]
    const float* __restrict__ bias,   // [64]
    float* __restrict__ y)            // [8][64][256][64]
{
    extern __shared__ float smem[];
    float* Xs  = smem;                 // 256*33 = 8448
    float* X1s = Xs  + 8448;           // 8448
    float* As0 = X1s + 8448;           // 8192
    float* As1 = As0 + 8192;           // 8192
    float* WT  = As1 + 8192;           // 224*64 = 14336

    const int t  = threadIdx.x;
    const int l  = t & 31;
    const int w  = t >> 5;
    // nconv mapping
    const int f0 = l & 15;                        // rows {f0, f0+16}
    const int vb = (w << 4) + ((l >> 4) << 3);    // 8 cols
    // mix mapping
    const int mvb = (w << 4) + ((l >> 3) & 3) * 4; // 4 v
    const int ob  = (l & 7) * 8;                   // 8 o
    const int bm = blockIdx.x;
    const int b  = bm >> 6;
    const int m  = bm & 63;

    // WT[c][o] = W[o][c]  (one-time transpose; W is L2-resident across CTAs)
    for (int i = t; i < CO * CC; i += 512) {
        int c = i >> 6, o = i & 63;
        WT[i] = W[o * CC + c];
    }
    // Xs (transposed): XT[n][f] = x[b][f][n][m]
    for (int i = t; i < F_ * NN; i += 512) {
        int f = i >> 8, n = i & 255;
        Xs[n * XP + f] = x[(((size_t)b * F_ + f) * NN + n) * MM + m];
    }
    __syncthreads();

    u64 yacc[4][4];
    {
        const float2* b2 = (const float2*)bias;
#pragma unroll
        for (int p = 0; p < 4; ++p) {
            float2 bb = b2[(ob >> 1) + p];
            u64 bp = pack2(bb.x, bb.y);
#pragma unroll
            for (int jj = 0; jj < 4; ++jj) yacc[jj][p] = bp;
        }
    }

    // slot 0: Y += W[:,0:32] * X
    mix_step(Xs, WT, 0, yacc, mvb, ob);

    const float* bases[3] = { base0, base1, base2 };
#pragma unroll 1
    for (int iB = 0; iB < 3; ++iB) {
        const float* Ag = bases[iB] + (size_t)bm * (NN * NN);

        nconv_step(Ag, Xs, X1s, As0, As1, t, f0, vb);
        mix_step(X1s, WT, 32 + iB * 64, yacc, mvb, ob);

        nconv_step(Ag, X1s, X1s, As0, As1, t, f0, vb);   // in-place, reg-accumulated
        mix_step(X1s, WT, 64 + iB * 64, yacc, mvb, ob);
    }

    // Store y[b][o][v][m]
#pragma unroll
    for (int jj = 0; jj < 4; ++jj) {
        int v = mvb + jj;
#pragma unroll
        for (int p = 0; p < 4; ++p) {
            float2 yv = unpk2(yacc[jj][p]);
            y[(((size_t)b * CO + ob + 2 * p    ) * NN + v) * MM + m] = yv.x;
            y[(((size_t)b * CO + ob + 2 * p + 1) * NN + v) * MM + m] = yv.y;
        }
    }
}

extern "C" void kernel_launch(void* const* d_in, const int* in_sizes, int n_in,
                              void* d_out, int out_size)
{
    const float* x     = (const float*)d_in[0];
    const float* base0 = (const float*)d_in[1];
    const float* base1 = (const float*)d_in[2];
    const float* base2 = (const float*)d_in[3];
    const float* W     = (const float*)d_in[4];
    const float* bias  = (const float*)d_in[5];
    float* y = (float*)d_out;

    const int smem_bytes = (8448 * 2 + 8192 * 2 + 14336) * (int)sizeof(float); // 190464
    cudaFuncSetAttribute(gcn_fused_kernel,
                         cudaFuncAttributeMaxDynamicSharedMemorySize, smem_bytes);

    gcn_fused_kernel<<<B_ * MM, 512, smem_bytes>>>(x, base0, base1, base2, W, bias, y);
}

// round 11
// speedup vs baseline: 1.0904x; 1.0904x over previous
#include <cuda_runtime.h>
#include <cstdint>

// Problem constants
#define B_   8
#define F_   32
#define NN   256
#define MM   64
#define CO   64
#define CC   224

typedef unsigned long long u64;

// ---- packed f32x2 helpers ----
__device__ __forceinline__ u64 pack2(float lo, float hi) {
    u64 r; asm("mov.b64 %0, {%1, %2};" : "=l"(r) : "f"(lo), "f"(hi)); return r;
}
__device__ __forceinline__ float2 unpk2(u64 v) {
    float2 f; asm("mov.b64 {%0, %1}, %2;" : "=f"(f.x), "=f"(f.y) : "l"(v)); return f;
}
__device__ __forceinline__ u64 ffma2(u64 a, u64 b, u64 c) {
    u64 d; asm("fma.rn.f32x2 %0, %1, %2, %3;" : "=l"(d) : "l"(a), "l"(b), "l"(c)); return d;
}

// ---- cp.async ----
__device__ __forceinline__ void cp_async16(void* smem_dst, const void* gmem_src) {
    uint32_t s = (uint32_t)__cvta_generic_to_shared(smem_dst);
    asm volatile("cp.async.cg.shared.global [%0], [%1], 16;\n" :: "r"(s), "l"(gmem_src));
}
__device__ __forceinline__ void cp_commit() { asm volatile("cp.async.commit_group;\n"); }
template <int N>
__device__ __forceinline__ void cp_wait() { asm volatile("cp.async.wait_group %0;\n" :: "n"(N)); }

__device__ __forceinline__ void issue_panel_copy(float* dst, const float* src, int t) {
    const float4* s4 = (const float4*)src;
    float4* d4 = (float4*)dst;
#pragma unroll
    for (int i = 0; i < 4; ++i)
        cp_async16(&d4[t + 512 * i], &s4[t + 512 * i]);
    cp_commit();
}

// X1[f][v] = sum_n X[f][n] * A[n][v].  X tiles row-major [32][256].
// Thread (w = t>>5, l = t&31): rows {w, w+16}, cols {4l..4l+3} U {4l+128..4l+131}.
// X reads are warp broadcasts; A reads are consecutive-16B LDS.128 (conflict-free).
__device__ __forceinline__ void nconv_step(
    const float* __restrict__ Ag,    // global A[b][m]: [256][256]
    const float* Xsrc, float* Xdst,  // smem [32][256] (may alias)
    float* As0, float* As1,
    int t, int w, int l)
{
    const int c0 = 4 * l;
    const int c1 = 4 * l + 128;

    u64 acc[2][4];   // [row r][pair: c0lo, c0hi, c1lo, c1hi]
#pragma unroll
    for (int r = 0; r < 2; ++r)
#pragma unroll
        for (int p = 0; p < 4; ++p) acc[r][p] = 0ull;

    float* bufs[2] = { As0, As1 };
    issue_panel_copy(As0, Ag, t);

#pragma unroll 1
    for (int kp = 0; kp < 8; ++kp) {
        if (kp < 7) {
            issue_panel_copy(bufs[(kp + 1) & 1], Ag + (kp + 1) * 8192, t);
            cp_wait<1>();
        } else {
            cp_wait<0>();
        }
        __syncthreads();

        const float* As = bufs[kp & 1];
        const float* Xr0 = Xsrc + w * NN + kp * 32;
        const float* Xr1 = Xsrc + (w + 16) * NN + kp * 32;

#pragma unroll 4
        for (int kk = 0; kk < 8; ++kk) {
            float4 xa = *(const float4*)&Xr0[kk * 4];   // broadcast
            float4 xb = *(const float4*)&Xr1[kk * 4];   // broadcast
#pragma unroll
            for (int j = 0; j < 4; ++j) {
                int k = kk * 4 + j;
                ulonglong2 a0 = *(const ulonglong2*)&As[k * NN + c0];
                ulonglong2 a1 = *(const ulonglong2*)&As[k * NN + c1];
                float xaj = (j == 0) ? xa.x : (j == 1) ? xa.y : (j == 2) ? xa.z : xa.w;
                float xbj = (j == 0) ? xb.x : (j == 1) ? xb.y : (j == 2) ? xb.z : xb.w;
                u64 xad = pack2(xaj, xaj);
                u64 xbd = pack2(xbj, xbj);
                acc[0][0] = ffma2(xad, a0.x, acc[0][0]);
                acc[0][1] = ffma2(xad, a0.y, acc[0][1]);
                acc[0][2] = ffma2(xad, a1.x, acc[0][2]);
                acc[0][3] = ffma2(xad, a1.y, acc[0][3]);
                acc[1][0] = ffma2(xbd, a0.x, acc[1][0]);
                acc[1][1] = ffma2(xbd, a0.y, acc[1][1]);
                acc[1][2] = ffma2(xbd, a1.x, acc[1][2]);
                acc[1][3] = ffma2(xbd, a1.y, acc[1][3]);
            }
        }
        __syncthreads();   // panel consumed; buffer reused at kp+2
    }

    // All reads of Xsrc done at the barrier above -> in-place safe.
#pragma unroll
    for (int r = 0; r < 2; ++r) {
        int row = w + 16 * r;
        float2 p0 = unpk2(acc[r][0]), p1 = unpk2(acc[r][1]);
        float2 p2 = unpk2(acc[r][2]), p3 = unpk2(acc[r][3]);
        *(float4*)&Xdst[row * NN + c0] = make_float4(p0.x, p0.y, p1.x, p1.y);
        *(float4*)&Xdst[row * NN + c1] = make_float4(p2.x, p2.y, p3.x, p3.y);
    }
    __syncthreads();
}

// Y[o][v] += sum_c W[o][cb+c] * Bs[c][v].
// Thread: 8 o's (4 packed pairs from WT) x 4 v's (dup'd h).
__device__ __forceinline__ void mix_step(
    const float* Bs,                 // smem [32][256]
    const float* WT,                 // smem W^T [224][64]
    int cb,
    u64 (&yacc)[4][4],
    int vb4, int ob)
{
#pragma unroll 4
    for (int c = 0; c < 32; ++c) {
        ulonglong2 w01 = *(const ulonglong2*)&WT[(cb + c) * 64 + ob];
        ulonglong2 w23 = *(const ulonglong2*)&WT[(cb + c) * 64 + ob + 4];
        float4 h = *(const float4*)&Bs[c * NN + vb4];
#pragma unroll
        for (int jj = 0; jj < 4; ++jj) {
            float hv = (jj == 0) ? h.x : (jj == 1) ? h.y : (jj == 2) ? h.z : h.w;
            u64 hd = pack2(hv, hv);
            yacc[jj][0] = ffma2(hd, w01.x, yacc[jj][0]);
            yacc[jj][1] = ffma2(hd, w01.y, yacc[jj][1]);
            yacc[jj][2] = ffma2(hd, w23.x, yacc[jj][2]);
            yacc[jj][3] = ffma2(hd, w23.y, yacc[jj][3]);
        }
    }
}

__global__ __launch_bounds__(512, 1)
void gcn_fused_kernel(
    const float* __restrict__ x,      // [8][32][256][64]
    const float* __restrict__ base0,  // [8][64][256][256]
    const float* __restrict__ base1,
    const float* __restrict__ base2,
    const float* __restrict__ W,      // [64][224]
    const float* __restrict__ bias,   // [64]
    float* __restrict__ y)            // [8][64][256][64]
{
    extern __shared__ float smem[];
    float* Xs  = smem;                 // 8192
    float* X1s = Xs  + 8192;           // 8192
    float* As0 = X1s + 8192;           // 8192
    float* As1 = As0 + 8192;           // 8192
    float* WT  = As1 + 8192;           // 224*64 = 14336  -> total 47104 fl = 184 KB

    const int t = threadIdx.x;
    const int w = t >> 5;
    const int l = t & 31;
    // mix mapping: 8 o's, 4 v's
    const int ob  = (l & 7) * 8;
    const int vb4 = (w * 4 + (l >> 3)) * 4;

    const int bm = blockIdx.x;
    const int b  = bm >> 6;
    const int m  = bm & 63;

    // WT[c][o] = W[o][c]
    for (int i = t; i < CO * CC; i += 512) {
        int c = i >> 6, o = i & 63;
        WT[i] = W[o * CC + c];
    }
    // Xs[f][n] = x[b][f][n][m]
    for (int i = t; i < F_ * NN; i += 512) {
        int f = i >> 8, n = i & 255;
        Xs[f * NN + n] = x[(((size_t)b * F_ + f) * NN + n) * MM + m];
    }
    __syncthreads();

    u64 yacc[4][4];
    {
        const ulonglong2* b2 = (const ulonglong2*)(bias + ob);
        ulonglong2 bb01 = b2[0], bb23 = b2[1];
#pragma unroll
        for (int jj = 0; jj < 4; ++jj) {
            yacc[jj][0] = bb01.x; yacc[jj][1] = bb01.y;
            yacc[jj][2] = bb23.x; yacc[jj][3] = bb23.y;
        }
    }

    // slot 0: Y += W[:,0:32] * X
    mix_step(Xs, WT, 0, yacc, vb4, ob);

    const float* bases[3] = { base0, base1, base2 };
#pragma unroll 1
    for (int iB = 0; iB < 3; ++iB) {
        const float* Ag = bases[iB] + (size_t)bm * (NN * NN);

        nconv_step(Ag, Xs, X1s, As0, As1, t, w, l);
        mix_step(X1s, WT, 32 + iB * 64, yacc, vb4, ob);

        nconv_step(Ag, X1s, X1s, As0, As1, t, w, l);  // in-place, reg-accumulated
        mix_step(X1s, WT, 64 + iB * 64, yacc, vb4, ob);
    }

    // Store y[b][o][v][m]
#pragma unroll
    for (int jj = 0; jj < 4; ++jj) {
        int v = vb4 + jj;
#pragma unroll
        for (int p = 0; p < 4; ++p) {
            float2 yv = unpk2(yacc[jj][p]);
            y[(((size_t)b * CO + ob + 2 * p    ) * NN + v) * MM + m] = yv.x;
            y[(((size_t)b * CO + ob + 2 * p + 1) * NN + v) * MM + m] = yv.y;
        }
    }
}

extern "C" void kernel_launch(void* const* d_in, const int* in_sizes, int n_in,
                              void* d_out, int out_size)
{
    const float* x     = (const float*)d_in[0];
    const float* base0 = (const float*)d_in[1];
    const float* base1 = (const float*)d_in[2];
    const float* base2 = (const float*)d_in[3];
    const float* W     = (const float*)d_in[4];
    const float* bias  = (const float*)d_in[5];
    float* y = (float*)d_out;

    const int smem_bytes = (8192 * 4 + 14336) * (int)sizeof(float);  // 188416
    cudaFuncSetAttribute(gcn_fused_kernel,
                         cudaFuncAttributeMaxDynamicSharedMemorySize, smem_bytes);

    gcn_fused_kernel<<<B_ * MM, 512, smem_bytes>>>(x, base0, base1, base2, W, bias, y);
}